// round 15
// baseline (speedup 1.0000x reference)
#include <cuda_runtime.h>
#include <cuda_fp16.h>

#define N_NODES 100000
#define N_EDGES 1600000
#define C_IN    128
#define C       64
#define HID3    256
#define SCAN_B  512
#define SCAN_NB 196   // ceil(100000/512)

// ---------------- scratch (device globals; no allocation allowed) ----------
__device__ int     g_is64;
__device__ int     g_deg[N_NODES];
__device__ float   g_dinv[N_NODES];
__device__ int     g_rowptr[N_NODES + 1];
__device__ int     g_writepos[N_NODES];
__device__ int     g_blocksums[SCAN_B];
__device__ int     g_colsrc[N_EDGES];
__device__ __half2 g_bufA[N_NODES * 32];   // h*dinv, fp16 (gather payload)
__device__ float   g_bufB[N_NODES * C];    // aggregation outputs (fp32)
__device__ float   g_Wc[C * C];            // W3@W4 folded
__device__ float   g_bc[C];                // b3@W4 + b4 folded

// ---------------- helpers ----------------------------------------------------
__device__ __forceinline__ unsigned tf32r(float f) {      // round-to-nearest tf32
    unsigned r;
    asm("cvt.rna.tf32.f32 %0, %1;" : "=r"(r) : "f"(f));
    return r;
}
__device__ __forceinline__ void mma_tf32(float c[4], const unsigned a[4],
                                         unsigned b0, unsigned b1) {
    asm("mma.sync.aligned.m16n8k8.row.col.f32.tf32.tf32.f32 "
        "{%0,%1,%2,%3}, {%4,%5,%6,%7}, {%8,%9}, {%0,%1,%2,%3};"
        : "+f"(c[0]), "+f"(c[1]), "+f"(c[2]), "+f"(c[3])
        : "r"(a[0]), "r"(a[1]), "r"(a[2]), "r"(a[3]), "r"(b0), "r"(b1));
}

// ---------------- zero deg + dtype probe ------------------------------------
__global__ void k_zero_probe(const int* __restrict__ ei32) {
    int i = blockIdx.x * blockDim.x + threadIdx.x;
    if (i < N_NODES) g_deg[i] = 0;
    if (i == 0) {
        int all_hi_zero = 1;
        #pragma unroll 1
        for (int j = 0; j < 256; j++)
            if (ei32[2 * j + 1] != 0) { all_hi_zero = 0; break; }
        g_is64 = all_hi_zero;
    }
}

// histogram of dst only (reads just the second half of edge_index)
__global__ void k_build(const void* __restrict__ ei) {
    int e = blockIdx.x * blockDim.x + threadIdx.x;
    if (e >= N_EDGES) return;
    int d;
    if (g_is64) d = (int)((const long long*)ei)[N_EDGES + e];
    else        d = ((const int*)ei)[N_EDGES + e];
    if ((unsigned)d >= N_NODES) d = 0;
    atomicAdd(&g_deg[d], 1);
}

// exclusive scan of g_deg -> g_rowptr (3-phase block scan); also emits dinv
__global__ void k_scan1() {
    __shared__ int sh[SCAN_B];
    int t = threadIdx.x;
    int i = blockIdx.x * SCAN_B + t;
    int v = (i < N_NODES) ? g_deg[i] : 0;
    if (i < N_NODES) g_dinv[i] = rsqrtf((float)v + 1.0f);
    sh[t] = v;
    __syncthreads();
    for (int off = 1; off < SCAN_B; off <<= 1) {
        int add = (t >= off) ? sh[t - off] : 0;
        __syncthreads();
        sh[t] += add;
        __syncthreads();
    }
    if (i < N_NODES) g_rowptr[i] = sh[t] - v;   // exclusive
    if (t == SCAN_B - 1) g_blocksums[blockIdx.x] = sh[t];
}

__global__ void k_scan2() {
    __shared__ int sh[SCAN_B];
    int t = threadIdx.x;
    int v = (t < SCAN_NB) ? g_blocksums[t] : 0;
    sh[t] = v;
    __syncthreads();
    for (int off = 1; off < SCAN_B; off <<= 1) {
        int add = (t >= off) ? sh[t - off] : 0;
        __syncthreads();
        sh[t] += add;
        __syncthreads();
    }
    if (t < SCAN_NB) g_blocksums[t] = sh[t] - v;
}

__global__ void k_scan3() {
    int i = blockIdx.x * SCAN_B + threadIdx.x;
    if (i < N_NODES) {
        int r = g_rowptr[i] + g_blocksums[blockIdx.x];
        g_rowptr[i]   = r;
        g_writepos[i] = r;
    }
    if (i == 0) g_rowptr[N_NODES] = N_EDGES;
}

__global__ void k_fill(const void* __restrict__ ei) {
    int e = blockIdx.x * blockDim.x + threadIdx.x;
    if (e >= N_EDGES) return;
    int s, d;
    if (g_is64) {
        const long long* p = (const long long*)ei;
        s = (int)p[e];
        d = (int)p[N_EDGES + e];
    } else {
        const int* p = (const int*)ei;
        s = p[e];
        d = p[N_EDGES + e];
    }
    if ((unsigned)s >= N_NODES || (unsigned)d >= N_NODES) { s = 0; d = 0; }
    int p2 = atomicAdd(&g_writepos[d], 1);
    g_colsrc[p2] = s;
}

// ---------------- folded linear weights, parallel over K --------------------
__global__ void k_wc(const float* __restrict__ W3, const float* __restrict__ W4,
                     const float* __restrict__ b3, const float* __restrict__ b4) {
    __shared__ float w3row[HID3];
    __shared__ float part[4][C];
    int c  = threadIdx.x & 63;
    int jq = threadIdx.x >> 6;           // 0..3
    if (blockIdx.x < 64) {
        int i = blockIdx.x;
        w3row[threadIdx.x] = W3[i * HID3 + threadIdx.x];
        __syncthreads();
        float acc = 0.0f;
        #pragma unroll 8
        for (int jj = 0; jj < 64; jj++) {
            int j = jq * 64 + jj;
            acc = fmaf(w3row[j], W4[j * C + c], acc);
        }
        part[jq][c] = acc;
        __syncthreads();
        if (jq == 0)
            g_Wc[i * C + c] = (part[0][c] + part[1][c]) + (part[2][c] + part[3][c]);
    } else {
        float acc = 0.0f;
        #pragma unroll 8
        for (int jj = 0; jj < 64; jj++) {
            int j = jq * 64 + jj;
            acc = fmaf(b3[j], W4[j * C + c], acc);
        }
        part[jq][c] = acc;
        __syncthreads();
        if (jq == 0)
            g_bc[c] = (part[0][c] + part[1][c]) + (part[2][c] + part[3][c]) + b4[c];
    }
}

// ---------------- tensor-core GEMM: Y[64-tile][64] = X @ W ------------------
// mma.sync.m16n8k8 tf32, fp32 accum. 128 thr = 4 warps in 2x2 grid over a
// 64x64 tile; each warp: 2 m-tiles x 4 n-tiles. Inputs rna-rounded to tf32 at
// smem-fill. MODE 0: X=x(K=128) -> bufA fp16*dinv; MODE 1: X=bufB(K=64) ->
// bufA fp16*dinv; MODE 2: X=bufB, W=g_Wc -> +bc, fused log_softmax -> Out.
template <int K, int MODE>
__global__ void k_gemm(const float* __restrict__ Xext, const float* __restrict__ Wext,
                       float* __restrict__ Out) {
    __shared__ float Xs[64][65];   // [row][k], padded
    __shared__ float Ws[64][65];   // [k][n],  padded
    const float* X = (MODE == 0) ? Xext : g_bufB;
    const float* W = (MODE == 2) ? g_Wc : Wext;

    int tid  = threadIdx.x;
    int warp = tid >> 5;
    int lane = tid & 31;
    int gid  = lane >> 2;          // 0..7
    int tig  = lane & 3;           // 0..3
    int wm   = (warp >> 1) * 32;   // warp row offset in tile
    int wn   = (warp & 1) * 32;    // warp col offset
    int row0 = blockIdx.x * 64;

    float acc[2][4][4] = {};       // [m-tile][n-tile][frag]

    for (int k0 = 0; k0 < K; k0 += 64) {
        #pragma unroll
        for (int idx = tid; idx < 64 * 16; idx += 128) {
            int r = idx >> 4, kq = idx & 15;
            int rr = min(row0 + r, N_NODES - 1);
            float4 v = *(const float4*)&X[rr * K + k0 + kq * 4];
            Xs[r][kq * 4 + 0] = __uint_as_float(tf32r(v.x));
            Xs[r][kq * 4 + 1] = __uint_as_float(tf32r(v.y));
            Xs[r][kq * 4 + 2] = __uint_as_float(tf32r(v.z));
            Xs[r][kq * 4 + 3] = __uint_as_float(tf32r(v.w));
        }
        #pragma unroll
        for (int idx = tid; idx < 64 * 16; idx += 128) {
            int kk = idx >> 4, cq = idx & 15;
            float4 v = *(const float4*)&W[(k0 + kk) * C + cq * 4];
            Ws[kk][cq * 4 + 0] = __uint_as_float(tf32r(v.x));
            Ws[kk][cq * 4 + 1] = __uint_as_float(tf32r(v.y));
            Ws[kk][cq * 4 + 2] = __uint_as_float(tf32r(v.z));
            Ws[kk][cq * 4 + 3] = __uint_as_float(tf32r(v.w));
        }
        __syncthreads();
        #pragma unroll
        for (int ks = 0; ks < 8; ks++) {
            int kc = ks * 8 + tig;
            unsigned a[2][4];
            #pragma unroll
            for (int mt = 0; mt < 2; mt++) {
                int m = wm + mt * 16 + gid;
                a[mt][0] = __float_as_uint(Xs[m][kc]);
                a[mt][1] = __float_as_uint(Xs[m + 8][kc]);
                a[mt][2] = __float_as_uint(Xs[m][kc + 4]);
                a[mt][3] = __float_as_uint(Xs[m + 8][kc + 4]);
            }
            #pragma unroll
            for (int nt = 0; nt < 4; nt++) {
                int n = wn + nt * 8 + gid;
                unsigned b0 = __float_as_uint(Ws[ks * 8 + tig][n]);
                unsigned b1 = __float_as_uint(Ws[ks * 8 + tig + 4][n]);
                mma_tf32(acc[0][nt], a[0], b0, b1);
                mma_tf32(acc[1][nt], a[1], b0, b1);
            }
        }
        __syncthreads();
    }

    if (MODE != 2) {
        #pragma unroll
        for (int mt = 0; mt < 2; mt++) {
            int r0 = row0 + wm + mt * 16 + gid;
            int r1 = r0 + 8;
            float s0 = (r0 < N_NODES) ? g_dinv[r0] : 0.0f;
            float s1 = (r1 < N_NODES) ? g_dinv[r1] : 0.0f;
            #pragma unroll
            for (int nt = 0; nt < 4; nt++) {
                int col = wn + nt * 8 + 2 * tig;
                if (r0 < N_NODES)
                    g_bufA[r0 * 32 + col / 2] =
                        __floats2half2_rn(acc[mt][nt][0] * s0, acc[mt][nt][1] * s0);
                if (r1 < N_NODES)
                    g_bufA[r1 * 32 + col / 2] =
                        __floats2half2_rn(acc[mt][nt][2] * s1, acc[mt][nt][3] * s1);
            }
        }
    } else {
        // stage logits (+bc) into Xs, then fused row log_softmax
        #pragma unroll
        for (int mt = 0; mt < 2; mt++) {
            int lr0 = wm + mt * 16 + gid;
            #pragma unroll
            for (int nt = 0; nt < 4; nt++) {
                int col = wn + nt * 8 + 2 * tig;
                Xs[lr0][col]     = acc[mt][nt][0] + g_bc[col];
                Xs[lr0][col + 1] = acc[mt][nt][1] + g_bc[col + 1];
                Xs[lr0 + 8][col]     = acc[mt][nt][2] + g_bc[col];
                Xs[lr0 + 8][col + 1] = acc[mt][nt][3] + g_bc[col + 1];
            }
        }
        __syncthreads();
        #pragma unroll 4
        for (int j = 0; j < 16; j++) {
            int r = warp * 16 + j;
            int rg2 = row0 + r;
            float y0 = Xs[r][lane];
            float y1 = Xs[r][lane + 32];
            float m = fmaxf(y0, y1);
            #pragma unroll
            for (int off = 16; off; off >>= 1)
                m = fmaxf(m, __shfl_xor_sync(0xffffffffu, m, off));
            float se = expf(y0 - m) + expf(y1 - m);
            #pragma unroll
            for (int off = 16; off; off >>= 1)
                se += __shfl_xor_sync(0xffffffffu, se, off);
            float lse = m + logf(se);
            if (rg2 < N_NODES) {
                Out[rg2 * C + lane]      = y0 - lse;
                Out[rg2 * C + lane + 32] = y1 - lse;
            }
        }
    }
}

// ---------------- CSR aggregation: bufB = relu(dinv*(sum+self) + b) --------
__global__ void k_agg(const float* __restrict__ bias) {
    int warp = (blockIdx.x * blockDim.x + threadIdx.x) >> 5;
    int lane = threadIdx.x & 31;
    if (warp >= N_NODES) return;

    const __half2* H = g_bufA;
    float2 acc = __half22float2(H[warp * 32 + lane]);   // self-loop term
    int beg = g_rowptr[warp];
    int end = g_rowptr[warp + 1];
    int e = beg;
    for (; e + 4 <= end; e += 4) {
        int s0 = g_colsrc[e + 0];
        int s1 = g_colsrc[e + 1];
        int s2 = g_colsrc[e + 2];
        int s3 = g_colsrc[e + 3];
        float2 v0 = __half22float2(H[s0 * 32 + lane]);
        float2 v1 = __half22float2(H[s1 * 32 + lane]);
        float2 v2 = __half22float2(H[s2 * 32 + lane]);
        float2 v3 = __half22float2(H[s3 * 32 + lane]);
        acc.x += (v0.x + v1.x) + (v2.x + v3.x);
        acc.y += (v0.y + v1.y) + (v2.y + v3.y);
    }
    for (; e < end; e++) {
        int s = g_colsrc[e];
        float2 v = __half22float2(H[s * 32 + lane]);
        acc.x += v.x;
        acc.y += v.y;
    }
    float d = g_dinv[warp];
    float2 b = ((const float2*)bias)[lane];
    float2 o;
    o.x = fmaxf(fmaf(acc.x, d, b.x), 0.0f);
    o.y = fmaxf(fmaf(acc.y, d, b.y), 0.0f);
    ((float2*)g_bufB)[warp * 32 + lane] = o;
}

// ---------------- launch ----------------------------------------------------
extern "C" void kernel_launch(void* const* d_in, const int* in_sizes, int n_in,
                              void* d_out, int out_size) {
    const float* x  = (const float*)d_in[0];
    const void*  ei = d_in[1];
    const float* W1 = (const float*)d_in[2];
    const float* b1 = (const float*)d_in[3];
    const float* W2 = (const float*)d_in[4];
    const float* b2 = (const float*)d_in[5];
    const float* W3 = (const float*)d_in[6];
    const float* b3 = (const float*)d_in[7];
    const float* W4 = (const float*)d_in[8];
    const float* b4 = (const float*)d_in[9];
    float* out = (float*)d_out;

    const int NODE_BLK = (N_NODES + 255) / 256;
    const int EDGE_BLK = (N_EDGES + 255) / 256;
    const int WARP_BLK = (N_NODES * 32 + 255) / 256;
    const int GEMM_BLK = (N_NODES + 63) / 64;   // 1563

    // CSR + degree preprocessing
    k_zero_probe<<<NODE_BLK, 256>>>((const int*)ei);
    k_build<<<EDGE_BLK, 256>>>(ei);
    k_scan1<<<SCAN_NB, SCAN_B>>>();
    k_scan2<<<1, SCAN_B>>>();
    k_scan3<<<SCAN_NB, SCAN_B>>>();
    k_fill<<<EDGE_BLK, 256>>>(ei);

    // Folded W3@W4 (parallel over K)
    k_wc<<<65, 256>>>(W3, W4, b3, b4);

    // Layer 1: h_s = (x@W1)*dinv ; agg+relu
    k_gemm<C_IN, 0><<<GEMM_BLK, 128>>>(x, W1, nullptr);
    k_agg<<<WARP_BLK, 256>>>(b1);

    // Layer 2: h_s = (relu1@W2)*dinv ; agg+relu
    k_gemm<C, 1><<<GEMM_BLK, 128>>>(x, W2, nullptr);
    k_agg<<<WARP_BLK, 256>>>(b2);

    // Folded linear + log_softmax (fused)
    k_gemm<C, 2><<<GEMM_BLK, 128>>>(x, W2, out);
}